// round 9
// baseline (speedup 1.0000x reference)
#include <cuda_runtime.h>
#include <cuda_fp16.h>
#include <cuda_bf16.h>
#include <math.h>
#include <stdint.h>

#define NN 2048
#define NFEAT 64
#define DD 256
#define HH 8
#define HDD 32
#define LL 6
#define FFND 1024
#define EE 32768
#define EFD 16
#define NFT 2049
#define MAXDEGC 64
#define D2 128
#define F2 512
#define BP 1025

__device__ float g_h[NFT * DD];
__device__ float g_fin[NFT * DD];
__device__ uint32_t g_hnh[NFT * D2], g_hnl[NFT * D2];
__device__ uint32_t g_qh[NFT * D2], g_ql[NFT * D2];
__device__ uint32_t g_kh[NFT * D2], g_kl[NFT * D2];
__device__ uint32_t g_vh[NFT * D2], g_vl[NFT * D2];
__device__ uint32_t g_oh[NFT * D2], g_ol[NFT * D2];
__device__ uint32_t g_fh[NFT * F2], g_fl[NFT * F2];
__device__ uint32_t g_biasb[(size_t)HH * NFT * BP];
#define WOFF_QKV 0
#define WOFF_O 589824
#define WOFF_F1 786432
#define WOFF_F2 1572864
#define WTOT 2359296
__device__ uint32_t g_wh[WTOT], g_wl[WTOT];
__device__ float g_qkvb[LL * 768];
__device__ int g_indeg[NN];
__device__ int g_outdeg[NN];

// ---------------------------------------------------------------------------
// helpers: fp16 hi/lo split
// ---------------------------------------------------------------------------
__device__ __forceinline__ void split2(float x0, float x1, uint32_t& hi, uint32_t& lo) {
    __half h0 = __float2half_rn(x0);
    __half h1 = __float2half_rn(x1);
    float r0 = x0 - __half2float(h0);
    float r1 = x1 - __half2float(h1);
    union { __half2 v; uint32_t u; } a, b;
    a.v = __halves2half2(h0, h1);
    b.v = __halves2half2(__float2half_rn(r0), __float2half_rn(r1));
    hi = a.u; lo = b.u;
}

__device__ __forceinline__ uint32_t pack_h2(float x0, float x1) {
    union { __half2 v; uint32_t u; } a;
    a.v = __floats2half2_rn(x0, x1);
    return a.u;
}

__device__ __forceinline__ void mma_hf(float c[4], uint32_t a0, uint32_t a1,
                                       uint32_t a2, uint32_t a3,
                                       uint32_t b0, uint32_t b1) {
    asm volatile(
        "mma.sync.aligned.m16n8k16.row.col.f32.f16.f16.f32 "
        "{%0,%1,%2,%3}, {%4,%5,%6,%7}, {%8,%9}, {%0,%1,%2,%3};"
        : "+f"(c[0]), "+f"(c[1]), "+f"(c[2]), "+f"(c[3])
        : "r"(a0), "r"(a1), "r"(a2), "r"(a3), "r"(b0), "r"(b1));
}

__device__ __forceinline__ uint32_t smem_u32(const void* p) {
    return (uint32_t)__cvta_generic_to_shared(p);
}

__device__ __forceinline__ void ldsm_x4(uint32_t& r0, uint32_t& r1,
                                        uint32_t& r2, uint32_t& r3, uint32_t addr) {
    asm volatile("ldmatrix.sync.aligned.m8n8.x4.shared.b16 {%0,%1,%2,%3}, [%4];"
                 : "=r"(r0), "=r"(r1), "=r"(r2), "=r"(r3) : "r"(addr));
}

// ---------------------------------------------------------------------------
// prep kernels
// ---------------------------------------------------------------------------
__global__ void split_prep_kernel(const float* __restrict__ src,
                                  uint32_t* __restrict__ dh,
                                  uint32_t* __restrict__ dl, int npairs) {
    int i = blockIdx.x * blockDim.x + threadIdx.x;
    if (i < npairs) {
        float2 v = *(const float2*)&src[2 * i];
        uint32_t h, l;
        split2(v.x, v.y, h, l);
        dh[i] = h; dl[i] = l;
    }
}

__global__ void split_qkv_kernel(const float* __restrict__ q_w,
                                 const float* __restrict__ k_w,
                                 const float* __restrict__ v_w,
                                 uint32_t* __restrict__ dh,
                                 uint32_t* __restrict__ dl) {
    int i = blockIdx.x * blockDim.x + threadIdx.x;
    if (i >= LL * 768 * 128) return;
    int l = i / (768 * 128);
    int rem = i - l * 768 * 128;
    int row = rem >> 7;
    int p = rem & 127;
    const float* src = (row < 256) ? q_w : (row < 512) ? k_w : v_w;
    int rr = row & 255;
    const float* sp = src + (size_t)l * DD * DD + (size_t)rr * DD + 2 * p;
    uint32_t h, lo;
    split2(sp[0], sp[1], h, lo);
    dh[i] = h; dl[i] = lo;
}

__global__ void qkvb_prep_kernel(const float* __restrict__ q_b,
                                 const float* __restrict__ k_b,
                                 const float* __restrict__ v_b) {
    int i = blockIdx.x * blockDim.x + threadIdx.x;
    if (i >= LL * 768) return;
    int l = i / 768, c = i % 768;
    float v = (c < 256) ? q_b[l * 256 + c]
            : (c < 512) ? k_b[l * 256 + (c - 256)]
                        : v_b[l * 256 + (c - 512)];
    g_qkvb[i] = v;
}

// ---------------------------------------------------------------------------
// degree counting / node embedding
// ---------------------------------------------------------------------------
__global__ void zero_deg_kernel() {
    int i = blockIdx.x * blockDim.x + threadIdx.x;
    if (i < NN) { g_indeg[i] = 0; g_outdeg[i] = 0; }
}

__global__ void count_deg_kernel(const int* __restrict__ edge_index) {
    int e = blockIdx.x * blockDim.x + threadIdx.x;
    if (e < EE) {
        atomicAdd(&g_outdeg[edge_index[e]], 1);
        atomicAdd(&g_indeg[edge_index[EE + e]], 1);
    }
}

__global__ void node_embed_kernel(const float* __restrict__ x,
                                  const float* __restrict__ W,
                                  const float* __restrict__ b,
                                  const float* __restrict__ inemb,
                                  const float* __restrict__ outemb) {
    int row = blockIdx.x;
    int col = threadIdx.x;
    __shared__ float xs[NFEAT];
    if (col < NFEAT) xs[col] = x[row * NFEAT + col];
    __syncthreads();
    float acc = 0.f;
#pragma unroll
    for (int k = 0; k < NFEAT; k++) acc += xs[k] * W[col * NFEAT + k];
    int ind = min(g_indeg[row], MAXDEGC);
    int outd = min(g_outdeg[row], MAXDEGC);
    g_h[(size_t)(row + 1) * DD + col] =
        acc + b[col] + inemb[ind * DD + col] + outemb[outd * DD + col];
}

__global__ void cls_kernel(const float* __restrict__ cls) {
    g_h[threadIdx.x] = cls[threadIdx.x];
}

// ---------------------------------------------------------------------------
// bias: direct bf16 fill + 16-bit CAS edge scatter
// ---------------------------------------------------------------------------
__global__ void bias_fillb_kernel(const int* __restrict__ dist,
                                  const float* __restrict__ dist_bias) {
    size_t idx = (size_t)blockIdx.x * blockDim.x + threadIdx.x;
    if (idx >= (size_t)HH * NFT * BP) return;
    int h = (int)(idx / ((size_t)NFT * BP));
    size_t rem = idx - (size_t)h * NFT * BP;
    int i = (int)(rem / BP);
    int p = (int)(rem % BP);
    int j0 = 2 * p, j1 = 2 * p + 1;
    int d0 = 0, d1 = 0;
    if (i > 0) {
        if (j0 > 0) {
            d0 = dist[(size_t)(i - 1) * NN + (j0 - 1)];
            d0 = max(0, min(d0, 9));
        }
        if (j1 > 0 && j1 < NFT) {
            d1 = dist[(size_t)(i - 1) * NN + (j1 - 1)];
            d1 = max(0, min(d1, 9));
        }
    }
    float v0 = dist_bias[d0 * HH + h];
    float v1 = (j1 < NFT) ? dist_bias[d1 * HH + h] : 0.f;
    union { __nv_bfloat162 v; uint32_t u; } a;
    a.v = __halves2bfloat162(__float2bfloat16_rn(v0), __float2bfloat16_rn(v1));
    g_biasb[idx] = a.u;
}

__device__ __forceinline__ void atomic_add_bf16half(uint32_t* addr, int hi, float val) {
    uint32_t old = *addr, assumed;
    do {
        assumed = old;
        unsigned short bits = hi ? (unsigned short)(assumed >> 16)
                                 : (unsigned short)(assumed & 0xffffu);
        __nv_bfloat16_raw r; r.x = bits;
        float cur = __bfloat162float((__nv_bfloat16)r);
        __nv_bfloat16 nb = __float2bfloat16_rn(cur + val);
        __nv_bfloat16_raw nr = static_cast<__nv_bfloat16_raw>(nb);
        uint32_t nw = hi ? ((assumed & 0x0000ffffu) | ((uint32_t)nr.x << 16))
                         : ((assumed & 0xffff0000u) | (uint32_t)nr.x);
        old = atomicCAS(addr, assumed, nw);
    } while (old != assumed);
}

__global__ void edge_bias_kernel(const float* __restrict__ edge_attr,
                                 const float* __restrict__ epw,
                                 const float* __restrict__ epb,
                                 const int* __restrict__ edge_index) {
    int e = blockIdx.x * blockDim.x + threadIdx.x;
    if (e >= EE) return;
    const float* ea = edge_attr + (size_t)e * EFD;
    int src = edge_index[e];
    int dst = edge_index[EE + e];
    int col = dst + 1;
    int p = col >> 1, hi = col & 1;
#pragma unroll
    for (int h = 0; h < HH; h++) {
        float pr = epb[h];
#pragma unroll
        for (int k = 0; k < EFD; k++) pr += ea[k] * epw[h * EFD + k];
        uint32_t* addr = &g_biasb[((size_t)h * NFT + src + 1) * BP + p];
        atomic_add_bf16half(addr, hi, pr);
    }
}

// ---------------------------------------------------------------------------
// warp-per-row layernorm
// ---------------------------------------------------------------------------
template <int SPLIT>
__global__ void ln_warp_kernel(const float* __restrict__ in,
                               float* __restrict__ outf,
                               uint32_t* __restrict__ oh, uint32_t* __restrict__ ol,
                               const float* __restrict__ s, const float* __restrict__ b) {
    int w = threadIdx.x >> 5, lane = threadIdx.x & 31;
    int row = blockIdx.x * 8 + w;
    if (row >= NFT) return;
    const float* p = in + (size_t)row * DD;
    float4 a = *(const float4*)&p[lane * 4];
    float4 c = *(const float4*)&p[128 + lane * 4];
    float sum = a.x + a.y + a.z + a.w + c.x + c.y + c.z + c.w;
#pragma unroll
    for (int o = 16; o > 0; o >>= 1) sum += __shfl_xor_sync(0xffffffffu, sum, o);
    float mean = sum * (1.0f / DD);
    float d0 = a.x - mean, d1 = a.y - mean, d2 = a.z - mean, d3 = a.w - mean;
    float d4 = c.x - mean, d5 = c.y - mean, d6 = c.z - mean, d7 = c.w - mean;
    float vs = d0 * d0 + d1 * d1 + d2 * d2 + d3 * d3 +
               d4 * d4 + d5 * d5 + d6 * d6 + d7 * d7;
#pragma unroll
    for (int o = 16; o > 0; o >>= 1) vs += __shfl_xor_sync(0xffffffffu, vs, o);
    float rstd = rsqrtf(vs * (1.0f / DD) + 1e-5f);
    int c0 = lane * 4, c1 = 128 + lane * 4;
    float o0 = d0 * rstd * s[c0 + 0] + b[c0 + 0];
    float o1 = d1 * rstd * s[c0 + 1] + b[c0 + 1];
    float o2 = d2 * rstd * s[c0 + 2] + b[c0 + 2];
    float o3 = d3 * rstd * s[c0 + 3] + b[c0 + 3];
    float o4 = d4 * rstd * s[c1 + 0] + b[c1 + 0];
    float o5 = d5 * rstd * s[c1 + 1] + b[c1 + 1];
    float o6 = d6 * rstd * s[c1 + 2] + b[c1 + 2];
    float o7 = d7 * rstd * s[c1 + 3] + b[c1 + 3];
    if (SPLIT) {
        uint32_t h, l;
        size_t base = (size_t)row * D2;
        split2(o0, o1, h, l); oh[base + 2 * lane] = h;      ol[base + 2 * lane] = l;
        split2(o2, o3, h, l); oh[base + 2 * lane + 1] = h;  ol[base + 2 * lane + 1] = l;
        split2(o4, o5, h, l); oh[base + 64 + 2 * lane] = h; ol[base + 64 + 2 * lane] = l;
        split2(o6, o7, h, l); oh[base + 65 + 2 * lane] = h; ol[base + 65 + 2 * lane] = l;
    } else {
        float* q = outf + (size_t)row * DD;
        *(float4*)&q[c0] = make_float4(o0, o1, o2, o3);
        *(float4*)&q[c1] = make_float4(o4, o5, o6, o7);
    }
}

// ---------------------------------------------------------------------------
// split GEMM, double-buffered smem, ldmatrix fragments (fp16 split, 3-MMA).
// MODE 0: split out. 1: fp32+res. 2: gelu+split. 3: fused-QKV epilogue.
// ---------------------------------------------------------------------------
#define GSTAGE (64 * 20 * 4)   // bytes per stage per array

template <int MODE>
__global__ void gemm_sp_kernel(const uint32_t* __restrict__ Ahg,
                               const uint32_t* __restrict__ Alg,
                               const uint32_t* __restrict__ Whg,
                               const uint32_t* __restrict__ Wlg,
                               const float* __restrict__ bias,
                               const float* __restrict__ res,
                               float* __restrict__ outf,
                               uint32_t* __restrict__ outh,
                               uint32_t* __restrict__ outl,
                               uint32_t* __restrict__ kh_, uint32_t* __restrict__ kl_,
                               uint32_t* __restrict__ vh_, uint32_t* __restrict__ vl_,
                               int M, int Ncol, int K) {
    __shared__ __align__(16) uint32_t Ah[2][64][20], Al[2][64][20];
    __shared__ __align__(16) uint32_t Bh[2][64][20], Bl[2][64][20];
    int K2 = K >> 1;
    int tid = threadIdx.x;
    int lane = tid & 31, wid = tid >> 5;
    int warpM = wid & 3, warpN = wid >> 2;
    int m0 = blockIdx.y * 64, n0 = blockIdx.x * 64;
    int g = lane >> 2, t = lane & 3;

    float c[4][4] = {};

    int lr = tid >> 2;
    int lq = (tid & 3) * 4;
    bool arow = (m0 + lr) < M;
    const uint4 z4 = make_uint4(0, 0, 0, 0);
    uint4 rah = arow ? *(const uint4*)&Ahg[(size_t)(m0 + lr) * K2 + lq] : z4;
    uint4 ral = arow ? *(const uint4*)&Alg[(size_t)(m0 + lr) * K2 + lq] : z4;
    uint4 rbh = *(const uint4*)&Whg[(size_t)(n0 + lr) * K2 + lq];
    uint4 rbl = *(const uint4*)&Wlg[(size_t)(n0 + lr) * K2 + lq];

    uint32_t a_h = smem_u32(&Ah[0][warpM * 16 + (lane & 15)][(lane >> 4) * 4]);
    uint32_t a_l = smem_u32(&Al[0][warpM * 16 + (lane & 15)][(lane >> 4) * 4]);
    int brow = warpN * 32 + (lane >> 4) * 8 + (lane & 7);
    int bseg = ((lane >> 3) & 1) * 4;
    uint32_t b_h0 = smem_u32(&Bh[0][brow][bseg]);
    uint32_t b_h1 = smem_u32(&Bh[0][brow + 16][bseg]);
    uint32_t b_l0 = smem_u32(&Bl[0][brow][bseg]);
    uint32_t b_l1 = smem_u32(&Bl[0][brow + 16][bseg]);

    // store stage 0
    {
        Ah[0][lr][lq] = rah.x; Ah[0][lr][lq + 1] = rah.y;
        Ah[0][lr][lq + 2] = rah.z; Ah[0][lr][lq + 3] = rah.w;
        Al[0][lr][lq] = ral.x; Al[0][lr][lq + 1] = ral.y;
        Al[0][lr][lq + 2] = ral.z; Al[0][lr][lq + 3] = ral.w;
        Bh[0][lr][lq] = rbh.x; Bh[0][lr][lq + 1] = rbh.y;
        Bh[0][lr][lq + 2] = rbh.z; Bh[0][lr][lq + 3] = rbh.w;
        Bl[0][lr][lq] = rbl.x; Bl[0][lr][lq + 1] = rbl.y;
        Bl[0][lr][lq + 2] = rbl.z; Bl[0][lr][lq + 3] = rbl.w;
    }
    __syncthreads();

    int stage = 0;
    for (int k0 = 0; k0 < K2; k0 += 16) {
        bool nxt = (k0 + 16) < K2;
        if (nxt) {
            rah = arow ? *(const uint4*)&Ahg[(size_t)(m0 + lr) * K2 + k0 + 16 + lq] : z4;
            ral = arow ? *(const uint4*)&Alg[(size_t)(m0 + lr) * K2 + k0 + 16 + lq] : z4;
            rbh = *(const uint4*)&Whg[(size_t)(n0 + lr) * K2 + k0 + 16 + lq];
            rbl = *(const uint4*)&Wlg[(size_t)(n0 + lr) * K2 + k0 + 16 + lq];
        }
        uint32_t so = stage * GSTAGE;
#pragma unroll
        for (int kk = 0; kk < 2; kk++) {
            uint32_t koff = so + kk * 32;
            uint32_t ah0, ah1, ah2, ah3, al0, al1, al2, al3;
            ldsm_x4(ah0, ah1, ah2, ah3, a_h + koff);
            ldsm_x4(al0, al1, al2, al3, a_l + koff);
            uint32_t bh[8], bl[8];
            ldsm_x4(bh[0], bh[1], bh[2], bh[3], b_h0 + koff);
            ldsm_x4(bh[4], bh[5], bh[6], bh[7], b_h1 + koff);
            ldsm_x4(bl[0], bl[1], bl[2], bl[3], b_l0 + koff);
            ldsm_x4(bl[4], bl[5], bl[6], bl[7], b_l1 + koff);
#pragma unroll
            for (int ni = 0; ni < 4; ni++) {
                uint32_t b0h = bh[ni * 2], b1h = bh[ni * 2 + 1];
                uint32_t b0l = bl[ni * 2], b1l = bl[ni * 2 + 1];
                mma_hf(c[ni], ah0, ah1, ah2, ah3, b0h, b1h);
                mma_hf(c[ni], ah0, ah1, ah2, ah3, b0l, b1l);
                mma_hf(c[ni], al0, al1, al2, al3, b0h, b1h);
            }
        }
        if (nxt) {
            int ns = stage ^ 1;
            Ah[ns][lr][lq] = rah.x; Ah[ns][lr][lq + 1] = rah.y;
            Ah[ns][lr][lq + 2] = rah.z; Ah[ns][lr][lq + 3] = rah.w;
            Al[ns][lr][lq] = ral.x; Al[ns][lr][lq + 1] = ral.y;
            Al[ns][lr][lq + 2] = ral.z; Al[ns][lr][lq + 3] = ral.w;
            Bh[ns][lr][lq] = rbh.x; Bh[ns][lr][lq + 1] = rbh.y;
            Bh[ns][lr][lq + 2] = rbh.z; Bh[ns][lr][lq + 3] = rbh.w;
            Bl[ns][lr][lq] = rbl.x; Bl[ns][lr][lq + 1] = rbl.y;
            Bl[ns][lr][lq + 2] = rbl.z; Bl[ns][lr][lq + 3] = rbl.w;
            __syncthreads();
            stage = ns;
        }
    }

    int N2 = Ncol >> 1;
#pragma unroll
    for (int ni = 0; ni < 4; ni++) {
        int col = n0 + warpN * 32 + ((ni < 2) ? 0 : 16) + (ni & 1) * 8 + t * 2;
        float b0 = bias[col], b1 = bias[col + 1];
#pragma unroll
        for (int half = 0; half < 2; half++) {
            int r = m0 + warpM * 16 + g + half * 8;
            if (r >= M) continue;
            float v0 = c[ni][half * 2 + 0] + b0;
            float v1 = c[ni][half * 2 + 1] + b1;
            if (MODE == 2) {
                v0 = 0.5f * v0 * (1.0f + erff(v0 * 0.7071067811865475f));
                v1 = 0.5f * v1 * (1.0f + erff(v1 * 0.7071067811865475f));
            }
            if (MODE == 1) {
                outf[(size_t)r * Ncol + col] = v0 + res[(size_t)r * Ncol + col];
                outf[(size_t)r * Ncol + col + 1] = v1 + res[(size_t)r * Ncol + col + 1];
            } else if (MODE == 3) {
                int buf = col >> 8, cc = col & 255;
                uint32_t* ph = (buf == 0) ? outh : (buf == 1) ? kh_ : vh_;
                uint32_t* pl = (buf == 0) ? outl : (buf == 1) ? kl_ : vl_;
                uint32_t hw, lw;
                split2(v0, v1, hw, lw);
                ph[(size_t)r * D2 + (cc >> 1)] = hw;
                pl[(size_t)r * D2 + (cc >> 1)] = lw;
            } else {
                uint32_t hw, lw;
                split2(v0, v1, hw, lw);
                outh[(size_t)r * N2 + (col >> 1)] = hw;
                outl[(size_t)r * N2 + (col >> 1)] = lw;
            }
        }
    }
}

// ---------------------------------------------------------------------------
// fused flash attention: 128 q-rows x 1 head, 256 threads (8 warps).
// K/V staging amortized over 2x rows vs R8; ldmatrix + direct-fp16 P.
// ---------------------------------------------------------------------------
__global__ void __launch_bounds__(256)
attn_kernel(const uint32_t* __restrict__ Qh, const uint32_t* __restrict__ Ql,
            const uint32_t* __restrict__ Khg, const uint32_t* __restrict__ Klg,
            const uint32_t* __restrict__ Vhg, const uint32_t* __restrict__ Vlg,
            const uint32_t* __restrict__ biasb,
            uint32_t* __restrict__ Oh, uint32_t* __restrict__ Ol) {
    __shared__ __align__(16) uint32_t Ksh[64][20], Ksl[64][20];
    __shared__ __align__(16) uint32_t Vsh[32][36], Vsl[32][36];

    int tid = threadIdx.x;
    int lane = tid & 31, w = tid >> 5;
    int g = lane >> 2, t = lane & 3;
    int z = blockIdx.y;
    int i0 = blockIdx.x * 128;
    int r0 = i0 + w * 16 + g;
    int r1 = r0 + 8;

    uint32_t qh[2][4], ql[2][4];
#pragma unroll
    for (int kk = 0; kk < 2; kk++) {
#pragma unroll
        for (int j = 0; j < 4; j++) {
            int rr = r0 + (j & 1) * 8;
            int pi = z * 16 + kk * 8 + (j >> 1) * 4 + t;
            qh[kk][j] = (rr < NFT) ? Qh[(size_t)rr * D2 + pi] : 0u;
            ql[kk][j] = (rr < NFT) ? Ql[(size_t)rr * D2 + pi] : 0u;
        }
    }

    float m[2] = {-1e30f, -1e30f}, l[2] = {0.f, 0.f};
    float co[4][4] = {};

    // staging maps (256 threads)
    int lkey = tid >> 2;           // 0..63 K row
    int lq = (tid & 3) * 4;        // K pair offset
    int kp = tid >> 3;             // 0..31 V key-pair
    int hp2 = (tid & 7) * 2;       // V hd-pair base

    const float inv = 0.17677669529663687f;
    int br0 = min(r0, NFT - 1), br1 = min(r1, NFT - 1);
    const uint32_t* bp0 = biasb + ((size_t)z * NFT + br0) * BP;
    const uint32_t* bp1 = biasb + ((size_t)z * NFT + br1) * BP;

    int krow = (lane >> 4) * 8 + (lane & 7);
    int kseg = ((lane >> 3) & 1) * 4;
    uint32_t k_h[4], k_l[4];
#pragma unroll
    for (int gg = 0; gg < 4; gg++) {
        k_h[gg] = smem_u32(&Ksh[gg * 16 + krow][kseg]);
        k_l[gg] = smem_u32(&Ksl[gg * 16 + krow][kseg]);
    }
    uint32_t v_h[2], v_l[2];
#pragma unroll
    for (int gg = 0; gg < 2; gg++) {
        v_h[gg] = smem_u32(&Vsh[gg * 16 + krow][kseg]);
        v_l[gg] = smem_u32(&Vsl[gg * 16 + krow][kseg]);
    }

    const uint4 z4 = make_uint4(0, 0, 0, 0);
    const uint2 z2 = make_uint2(0, 0);
    uint4 rkh, rkl;
    uint2 vah, val_, vbh, vbl;
    {
        bool kv = lkey < NFT;
        rkh = kv ? *(const uint4*)&Khg[(size_t)lkey * D2 + z * 16 + lq] : z4;
        rkl = kv ? *(const uint4*)&Klg[(size_t)lkey * D2 + z * 16 + lq] : z4;
        int ra = 2 * kp, rb = 2 * kp + 1;
        vah = (ra < NFT) ? *(const uint2*)&Vhg[(size_t)ra * D2 + z * 16 + hp2] : z2;
        val_ = (ra < NFT) ? *(const uint2*)&Vlg[(size_t)ra * D2 + z * 16 + hp2] : z2;
        vbh = (rb < NFT) ? *(const uint2*)&Vhg[(size_t)rb * D2 + z * 16 + hp2] : z2;
        vbl = (rb < NFT) ? *(const uint2*)&Vlg[(size_t)rb * D2 + z * 16 + hp2] : z2;
    }

    for (int jt = 0; jt < 33; jt++) {
        int j0 = jt * 64;
        __syncthreads();
        {
            Ksh[lkey][lq] = rkh.x; Ksh[lkey][lq + 1] = rkh.y;
            Ksh[lkey][lq + 2] = rkh.z; Ksh[lkey][lq + 3] = rkh.w;
            Ksl[lkey][lq] = rkl.x; Ksl[lkey][lq + 1] = rkl.y;
            Ksl[lkey][lq + 2] = rkl.z; Ksl[lkey][lq + 3] = rkl.w;
            Vsh[2 * hp2 + 0][kp] = __byte_perm(vah.x, vbh.x, 0x5410);
            Vsh[2 * hp2 + 1][kp] = __byte_perm(vah.x, vbh.x, 0x7632);
            Vsh[2 * hp2 + 2][kp] = __byte_perm(vah.y, vbh.y, 0x5410);
            Vsh[2 * hp2 + 3][kp] = __byte_perm(vah.y, vbh.y, 0x7632);
            Vsl[2 * hp2 + 0][kp] = __byte_perm(val_.x, vbl.x, 0x5410);
            Vsl[2 * hp2 + 1][kp] = __byte_perm(val_.x, vbl.x, 0x7632);
            Vsl[2 * hp2 + 2][kp] = __byte_perm(val_.y, vbl.y, 0x5410);
            Vsl[2 * hp2 + 3][kp] = __byte_perm(val_.y, vbl.y, 0x7632);
        }
        __syncthreads();
        if (jt + 1 < 33) {
            int n0 = (jt + 1) * 64;
            bool kv = n0 + lkey < NFT;
            rkh = kv ? *(const uint4*)&Khg[(size_t)(n0 + lkey) * D2 + z * 16 + lq] : z4;
            rkl = kv ? *(const uint4*)&Klg[(size_t)(n0 + lkey) * D2 + z * 16 + lq] : z4;
            int ra = n0 + 2 * kp, rb = ra + 1;
            vah = (ra < NFT) ? *(const uint2*)&Vhg[(size_t)ra * D2 + z * 16 + hp2] : z2;
            val_ = (ra < NFT) ? *(const uint2*)&Vlg[(size_t)ra * D2 + z * 16 + hp2] : z2;
            vbh = (rb < NFT) ? *(const uint2*)&Vhg[(size_t)rb * D2 + z * 16 + hp2] : z2;
            vbl = (rb < NFT) ? *(const uint2*)&Vlg[(size_t)rb * D2 + z * 16 + hp2] : z2;
        }

        // S = Q @ K^T
        float cs[8][4] = {};
#pragma unroll
        for (int kk = 0; kk < 2; kk++) {
            uint32_t koff = kk * 32;
#pragma unroll
            for (int gg = 0; gg < 4; gg++) {
                uint32_t f0, f1, f2, f3, e0, e1, e2, e3;
                ldsm_x4(f0, f1, f2, f3, k_h[gg] + koff);
                ldsm_x4(e0, e1, e2, e3, k_l[gg] + koff);
                mma_hf(cs[2 * gg], qh[kk][0], qh[kk][1], qh[kk][2], qh[kk][3], f0, f1);
                mma_hf(cs[2 * gg], qh[kk][0], qh[kk][1], qh[kk][2], qh[kk][3], e0, e1);
                mma_hf(cs[2 * gg], ql[kk][0], ql[kk][1], ql[kk][2], ql[kk][3], f0, f1);
                mma_hf(cs[2 * gg + 1], qh[kk][0], qh[kk][1], qh[kk][2], qh[kk][3], f2, f3);
                mma_hf(cs[2 * gg + 1], qh[kk][0], qh[kk][1], qh[kk][2], qh[kk][3], e2, e3);
                mma_hf(cs[2 * gg + 1], ql[kk][0], ql[kk][1], ql[kk][2], ql[kk][3], f2, f3);
            }
        }

        // scale + bias + guards
#pragma unroll
        for (int ni = 0; ni < 8; ni++) {
            int gg = ni >> 1;
            int col = j0 + gg * 16 + (ni & 1) * 8 + t * 2;
            int pidx = (col >> 1);
            union { uint32_t u; __nv_bfloat162 v; } w0, w1;
            w0.u = bp0[pidx]; w1.u = bp1[pidx];
            float2 f0 = __bfloat1622float2(w0.v);
            float2 f1 = __bfloat1622float2(w1.v);
            bool v0 = col < NFT, v1 = col + 1 < NFT;
            cs[ni][0] = v0 ? cs[ni][0] * inv + f0.x : -1e30f;
            cs[ni][1] = v1 ? cs[ni][1] * inv + f0.y : -1e30f;
            cs[ni][2] = v0 ? cs[ni][2] * inv + f1.x : -1e30f;
            cs[ni][3] = v1 ? cs[ni][3] * inv + f1.y : -1e30f;
        }

        // online softmax
#pragma unroll
        for (int hh = 0; hh < 2; hh++) {
            int c0 = hh * 2;
            float mx = -1e30f;
#pragma unroll
            for (int ni = 0; ni < 8; ni++)
                mx = fmaxf(mx, fmaxf(cs[ni][c0], cs[ni][c0 + 1]));
            mx = fmaxf(mx, __shfl_xor_sync(0xffffffffu, mx, 1));
            mx = fmaxf(mx, __shfl_xor_sync(0xffffffffu, mx, 2));
            float mn = fmaxf(m[hh], mx);
            float corr = __expf(m[hh] - mn);
            m[hh] = mn;
            l[hh] *= corr;
#pragma unroll
            for (int ni = 0; ni < 4; ni++) {
                co[ni][c0] *= corr;
                co[ni][c0 + 1] *= corr;
            }
            float sum = 0.f;
#pragma unroll
            for (int ni = 0; ni < 8; ni++) {
                float p0 = __expf(cs[ni][c0] - mn);
                float p1 = __expf(cs[ni][c0 + 1] - mn);
                cs[ni][c0] = p0; cs[ni][c0 + 1] = p1;
                sum += p0 + p1;
            }
            sum += __shfl_xor_sync(0xffffffffu, sum, 1);
            sum += __shfl_xor_sync(0xffffffffu, sum, 2);
            l[hh] += sum;
        }

        // O += P @ V : P direct fp16
#pragma unroll
        for (int kk = 0; kk < 4; kk++) {
            uint32_t a0 = pack_h2(cs[2 * kk][0], cs[2 * kk][1]);
            uint32_t a1 = pack_h2(cs[2 * kk][2], cs[2 * kk][3]);
            uint32_t a2 = pack_h2(cs[2 * kk + 1][0], cs[2 * kk + 1][1]);
            uint32_t a3 = pack_h2(cs[2 * kk + 1][2], cs[2 * kk + 1][3]);
            uint32_t koff = kk * 32;
#pragma unroll
            for (int gg = 0; gg < 2; gg++) {
                uint32_t f0, f1, f2, f3, e0, e1, e2, e3;
                ldsm_x4(f0, f1, f2, f3, v_h[gg] + koff);
                ldsm_x4(e0, e1, e2, e3, v_l[gg] + koff);
                mma_hf(co[2 * gg], a0, a1, a2, a3, f0, f1);
                mma_hf(co[2 * gg], a0, a1, a2, a3, e0, e1);
                mma_hf(co[2 * gg + 1], a0, a1, a2, a3, f2, f3);
                mma_hf(co[2 * gg + 1], a0, a1, a2, a3, e2, e3);
            }
        }
    }

    float inv0 = 1.f / l[0], inv1 = 1.f / l[1];
#pragma unroll
    for (int ni = 0; ni < 4; ni++) {
        int cc = (ni >> 1) * 16 + (ni & 1) * 8 + t * 2;
        int pi = z * 16 + (cc >> 1);
        if (r0 < NFT) {
            uint32_t hw, lw;
            split2(co[ni][0] * inv0, co[ni][1] * inv0, hw, lw);
            Oh[(size_t)r0 * D2 + pi] = hw;
            Ol[(size_t)r0 * D2 + pi] = lw;
        }
        if (r1 < NFT) {
            uint32_t hw, lw;
            split2(co[ni][2] * inv1, co[ni][3] * inv1, hw, lw);
            Oh[(size_t)r1 * D2 + pi] = hw;
            Ol[(size_t)r1 * D2 + pi] = lw;
        }
    }
}

// ---------------------------------------------------------------------------
// launch
// ---------------------------------------------------------------------------
extern "C" void kernel_launch(void* const* d_in, const int* in_sizes, int n_in,
                              void* d_out, int out_size) {
    const float* x            = (const float*)d_in[0];
    const float* edge_attr    = (const float*)d_in[1];
    const float* node_proj_w  = (const float*)d_in[2];
    const float* node_proj_b  = (const float*)d_in[3];
    const float* in_deg_emb   = (const float*)d_in[4];
    const float* out_deg_emb  = (const float*)d_in[5];
    const float* dist_bias    = (const float*)d_in[6];
    const float* edge_proj_w  = (const float*)d_in[7];
    const float* edge_proj_b  = (const float*)d_in[8];
    const float* cls_token    = (const float*)d_in[9];
    const float* q_w = (const float*)d_in[10];
    const float* q_b = (const float*)d_in[11];
    const float* k_w = (const float*)d_in[12];
    const float* k_b = (const float*)d_in[13];
    const float* v_w = (const float*)d_in[14];
    const float* v_b = (const float*)d_in[15];
    const float* o_w = (const float*)d_in[16];
    const float* o_b = (const float*)d_in[17];
    const float* ffn1_w = (const float*)d_in[18];
    const float* ffn1_b = (const float*)d_in[19];
    const float* ffn2_w = (const float*)d_in[20];
    const float* ffn2_b = (const float*)d_in[21];
    const float* ln1_s = (const float*)d_in[22];
    const float* ln1_b = (const float*)d_in[23];
    const float* ln2_s = (const float*)d_in[24];
    const float* ln2_b = (const float*)d_in[25];
    const float* fn_s = (const float*)d_in[26];
    const float* fn_b = (const float*)d_in[27];
    const int* edge_index  = (const int*)d_in[28];
    const int* dist_matrix = (const int*)d_in[29];
    float* out = (float*)d_out;

    float *h, *fin, *qkvb;
    uint32_t *hnh, *hnl, *qh, *ql, *kh, *kl, *vh, *vl, *oh, *ol, *fh, *fl;
    uint32_t *wh, *wl, *biasb;
    cudaGetSymbolAddress((void**)&h, g_h);
    cudaGetSymbolAddress((void**)&fin, g_fin);
    cudaGetSymbolAddress((void**)&hnh, g_hnh); cudaGetSymbolAddress((void**)&hnl, g_hnl);
    cudaGetSymbolAddress((void**)&qh, g_qh); cudaGetSymbolAddress((void**)&ql, g_ql);
    cudaGetSymbolAddress((void**)&kh, g_kh); cudaGetSymbolAddress((void**)&kl, g_kl);
    cudaGetSymbolAddress((void**)&vh, g_vh); cudaGetSymbolAddress((void**)&vl, g_vl);
    cudaGetSymbolAddress((void**)&oh, g_oh); cudaGetSymbolAddress((void**)&ol, g_ol);
    cudaGetSymbolAddress((void**)&fh, g_fh); cudaGetSymbolAddress((void**)&fl, g_fl);
    cudaGetSymbolAddress((void**)&wh, g_wh); cudaGetSymbolAddress((void**)&wl, g_wl);
    cudaGetSymbolAddress((void**)&biasb, g_biasb);
    cudaGetSymbolAddress((void**)&qkvb, g_qkvb);

    const int PQKV = LL * 768 * 128;
    const int DQ = LL * DD * DD / 2;
    const int DF = LL * FFND * DD / 2;
    split_qkv_kernel<<<(PQKV + 255) / 256, 256>>>(q_w, k_w, v_w, wh + WOFF_QKV, wl + WOFF_QKV);
    qkvb_prep_kernel<<<(LL * 768 + 255) / 256, 256>>>(q_b, k_b, v_b);
    split_prep_kernel<<<(DQ + 255) / 256, 256>>>(o_w, wh + WOFF_O, wl + WOFF_O, DQ);
    split_prep_kernel<<<(DF + 255) / 256, 256>>>(ffn1_w, wh + WOFF_F1, wl + WOFF_F1, DF);
    split_prep_kernel<<<(DF + 255) / 256, 256>>>(ffn2_w, wh + WOFF_F2, wl + WOFF_F2, DF);

    zero_deg_kernel<<<(NN + 255) / 256, 256>>>();
    count_deg_kernel<<<(EE + 255) / 256, 256>>>(edge_index);
    node_embed_kernel<<<NN, 256>>>(x, node_proj_w, node_proj_b, in_deg_emb, out_deg_emb);
    cls_kernel<<<1, 256>>>(cls_token);

    size_t nbp = (size_t)HH * NFT * BP;
    bias_fillb_kernel<<<(unsigned)((nbp + 255) / 256), 256>>>(dist_matrix, dist_bias);
    edge_bias_kernel<<<(EE + 255) / 256, 256>>>(edge_attr, edge_proj_w, edge_proj_b,
                                                edge_index);

    dim3 gemmQKV(12, 33);
    dim3 gemmD(4, 33);
    dim3 gemmF1(16, 33);
    dim3 attnG(17, 8);
    int lnG = (NFT + 7) / 8;

    for (int l = 0; l < LL; l++) {
        ln_warp_kernel<1><<<lnG, 256>>>(h, nullptr, hnh, hnl,
                                        ln1_s + l * DD, ln1_b + l * DD);
        gemm_sp_kernel<3><<<gemmQKV, 256>>>(hnh, hnl,
                                            wh + WOFF_QKV + (size_t)l * 98304,
                                            wl + WOFF_QKV + (size_t)l * 98304,
                                            qkvb + l * 768, nullptr, nullptr,
                                            qh, ql, kh, kl, vh, vl,
                                            NFT, 768, DD);
        attn_kernel<<<attnG, 256>>>(qh, ql, kh, kl, vh, vl, biasb, oh, ol);
        gemm_sp_kernel<1><<<gemmD, 256>>>(oh, ol,
                                          wh + WOFF_O + (size_t)l * 32768,
                                          wl + WOFF_O + (size_t)l * 32768,
                                          o_b + l * DD, h, h, nullptr, nullptr,
                                          nullptr, nullptr, nullptr, nullptr,
                                          NFT, DD, DD);
        ln_warp_kernel<1><<<lnG, 256>>>(h, nullptr, hnh, hnl,
                                        ln2_s + l * DD, ln2_b + l * DD);
        gemm_sp_kernel<2><<<gemmF1, 256>>>(hnh, hnl,
                                           wh + WOFF_F1 + (size_t)l * 131072,
                                           wl + WOFF_F1 + (size_t)l * 131072,
                                           ffn1_b + l * FFND, nullptr, nullptr, fh, fl,
                                           nullptr, nullptr, nullptr, nullptr,
                                           NFT, FFND, DD);
        gemm_sp_kernel<1><<<gemmD, 256>>>(fh, fl,
                                          wh + WOFF_F2 + (size_t)l * 131072,
                                          wl + WOFF_F2 + (size_t)l * 131072,
                                          ffn2_b + l * DD, h, h, nullptr, nullptr,
                                          nullptr, nullptr, nullptr, nullptr,
                                          NFT, DD, FFND);
    }

    ln_warp_kernel<0><<<lnG, 256>>>(h, fin, nullptr, nullptr, fn_s, fn_b);
    size_t total = (size_t)NFT * DD;
    if ((size_t)out_size >= total + DD) {
        cudaMemcpyAsync(out, fin, total * sizeof(float), cudaMemcpyDeviceToDevice);
        cudaMemcpyAsync(out + total, fin, DD * sizeof(float), cudaMemcpyDeviceToDevice);
    } else if ((size_t)out_size >= total) {
        cudaMemcpyAsync(out, fin, total * sizeof(float), cudaMemcpyDeviceToDevice);
    } else {
        cudaMemcpyAsync(out, fin, (size_t)out_size * sizeof(float),
                        cudaMemcpyDeviceToDevice);
    }
}

// round 10
// speedup vs baseline: 1.1403x; 1.1403x over previous
#include <cuda_runtime.h>
#include <cuda_fp16.h>
#include <cuda_bf16.h>
#include <math.h>
#include <stdint.h>

#define NN 2048
#define NFEAT 64
#define DD 256
#define HH 8
#define HDD 32
#define LL 6
#define FFND 1024
#define EE 32768
#define EFD 16
#define NFT 2049
#define MAXDEGC 64
#define D2 128
#define F2 512
#define BP 1025

__device__ float g_h[NFT * DD];
__device__ float g_fin[NFT * DD];
__device__ uint32_t g_hnh[NFT * D2], g_hnl[NFT * D2];
__device__ uint32_t g_qh[NFT * D2], g_ql[NFT * D2];
__device__ uint32_t g_kh[NFT * D2], g_kl[NFT * D2];
__device__ uint32_t g_vh[NFT * D2], g_vl[NFT * D2];
__device__ uint32_t g_oh[NFT * D2], g_ol[NFT * D2];
__device__ uint32_t g_fh[NFT * F2], g_fl[NFT * F2];
__device__ uint32_t g_biasb[(size_t)HH * NFT * BP];
#define WOFF_QKV 0
#define WOFF_O 589824
#define WOFF_F1 786432
#define WOFF_F2 1572864
#define WTOT 2359296
__device__ uint32_t g_wh[WTOT], g_wl[WTOT];
__device__ float g_qkvb[LL * 768];
__device__ int g_indeg[NN];
__device__ int g_outdeg[NN];

// ---------------------------------------------------------------------------
// helpers: fp16 hi/lo split
// ---------------------------------------------------------------------------
__device__ __forceinline__ void split2(float x0, float x1, uint32_t& hi, uint32_t& lo) {
    __half h0 = __float2half_rn(x0);
    __half h1 = __float2half_rn(x1);
    float r0 = x0 - __half2float(h0);
    float r1 = x1 - __half2float(h1);
    union { __half2 v; uint32_t u; } a, b;
    a.v = __halves2half2(h0, h1);
    b.v = __halves2half2(__float2half_rn(r0), __float2half_rn(r1));
    hi = a.u; lo = b.u;
}

__device__ __forceinline__ uint32_t pack_h2(float x0, float x1) {
    union { __half2 v; uint32_t u; } a;
    a.v = __floats2half2_rn(x0, x1);
    return a.u;
}

__device__ __forceinline__ void mma_hf(float c[4], uint32_t a0, uint32_t a1,
                                       uint32_t a2, uint32_t a3,
                                       uint32_t b0, uint32_t b1) {
    asm volatile(
        "mma.sync.aligned.m16n8k16.row.col.f32.f16.f16.f32 "
        "{%0,%1,%2,%3}, {%4,%5,%6,%7}, {%8,%9}, {%0,%1,%2,%3};"
        : "+f"(c[0]), "+f"(c[1]), "+f"(c[2]), "+f"(c[3])
        : "r"(a0), "r"(a1), "r"(a2), "r"(a3), "r"(b0), "r"(b1));
}

__device__ __forceinline__ uint32_t smem_u32(const void* p) {
    return (uint32_t)__cvta_generic_to_shared(p);
}

__device__ __forceinline__ void ldsm_x4(uint32_t& r0, uint32_t& r1,
                                        uint32_t& r2, uint32_t& r3, uint32_t addr) {
    asm volatile("ldmatrix.sync.aligned.m8n8.x4.shared.b16 {%0,%1,%2,%3}, [%4];"
                 : "=r"(r0), "=r"(r1), "=r"(r2), "=r"(r3) : "r"(addr));
}

// ---------------------------------------------------------------------------
// prep kernels
// ---------------------------------------------------------------------------
__global__ void split_prep_kernel(const float* __restrict__ src,
                                  uint32_t* __restrict__ dh,
                                  uint32_t* __restrict__ dl, int npairs) {
    int i = blockIdx.x * blockDim.x + threadIdx.x;
    if (i < npairs) {
        float2 v = *(const float2*)&src[2 * i];
        uint32_t h, l;
        split2(v.x, v.y, h, l);
        dh[i] = h; dl[i] = l;
    }
}

__global__ void split_qkv_kernel(const float* __restrict__ q_w,
                                 const float* __restrict__ k_w,
                                 const float* __restrict__ v_w,
                                 uint32_t* __restrict__ dh,
                                 uint32_t* __restrict__ dl) {
    int i = blockIdx.x * blockDim.x + threadIdx.x;
    if (i >= LL * 768 * 128) return;
    int l = i / (768 * 128);
    int rem = i - l * 768 * 128;
    int row = rem >> 7;
    int p = rem & 127;
    const float* src = (row < 256) ? q_w : (row < 512) ? k_w : v_w;
    int rr = row & 255;
    const float* sp = src + (size_t)l * DD * DD + (size_t)rr * DD + 2 * p;
    uint32_t h, lo;
    split2(sp[0], sp[1], h, lo);
    dh[i] = h; dl[i] = lo;
}

__global__ void qkvb_prep_kernel(const float* __restrict__ q_b,
                                 const float* __restrict__ k_b,
                                 const float* __restrict__ v_b) {
    int i = blockIdx.x * blockDim.x + threadIdx.x;
    if (i >= LL * 768) return;
    int l = i / 768, c = i % 768;
    float v = (c < 256) ? q_b[l * 256 + c]
            : (c < 512) ? k_b[l * 256 + (c - 256)]
                        : v_b[l * 256 + (c - 512)];
    g_qkvb[i] = v;
}

// ---------------------------------------------------------------------------
// degree counting / node embedding
// ---------------------------------------------------------------------------
__global__ void zero_deg_kernel() {
    int i = blockIdx.x * blockDim.x + threadIdx.x;
    if (i < NN) { g_indeg[i] = 0; g_outdeg[i] = 0; }
}

__global__ void count_deg_kernel(const int* __restrict__ edge_index) {
    int e = blockIdx.x * blockDim.x + threadIdx.x;
    if (e < EE) {
        atomicAdd(&g_outdeg[edge_index[e]], 1);
        atomicAdd(&g_indeg[edge_index[EE + e]], 1);
    }
}

__global__ void node_embed_kernel(const float* __restrict__ x,
                                  const float* __restrict__ W,
                                  const float* __restrict__ b,
                                  const float* __restrict__ inemb,
                                  const float* __restrict__ outemb) {
    int row = blockIdx.x;
    int col = threadIdx.x;
    __shared__ float xs[NFEAT];
    if (col < NFEAT) xs[col] = x[row * NFEAT + col];
    __syncthreads();
    float acc = 0.f;
#pragma unroll
    for (int k = 0; k < NFEAT; k++) acc += xs[k] * W[col * NFEAT + k];
    int ind = min(g_indeg[row], MAXDEGC);
    int outd = min(g_outdeg[row], MAXDEGC);
    g_h[(size_t)(row + 1) * DD + col] =
        acc + b[col] + inemb[ind * DD + col] + outemb[outd * DD + col];
}

__global__ void cls_kernel(const float* __restrict__ cls) {
    g_h[threadIdx.x] = cls[threadIdx.x];
}

// ---------------------------------------------------------------------------
// bias fill: one thread per (row, pair) cell; dist read ONCE, 8 head writes.
// ---------------------------------------------------------------------------
__global__ void bias_fillb_kernel(const int* __restrict__ dist,
                                  const float* __restrict__ dist_bias) {
    int idx = blockIdx.x * blockDim.x + threadIdx.x;
    if (idx >= NFT * BP) return;
    int i = idx / BP;
    int p = idx % BP;
    int j0 = 2 * p, j1 = 2 * p + 1;
    int d0 = 0, d1 = 0;
    if (i > 0) {
        if (j0 > 0) {
            d0 = dist[(size_t)(i - 1) * NN + (j0 - 1)];
            d0 = max(0, min(d0, 9));
        }
        if (j1 > 0 && j1 < NFT) {
            d1 = dist[(size_t)(i - 1) * NN + (j1 - 1)];
            d1 = max(0, min(d1, 9));
        }
    }
    bool j1v = (j1 < NFT);
    size_t base = (size_t)i * BP + p;
#pragma unroll
    for (int h = 0; h < HH; h++) {
        float v0 = dist_bias[d0 * HH + h];
        float v1 = j1v ? dist_bias[d1 * HH + h] : 0.f;
        union { __nv_bfloat162 v; uint32_t u; } a;
        a.v = __halves2bfloat162(__float2bfloat16_rn(v0), __float2bfloat16_rn(v1));
        g_biasb[(size_t)h * NFT * BP + base] = a.u;
    }
}

__device__ __forceinline__ void atomic_add_bf16half(uint32_t* addr, int hi, float val) {
    uint32_t old = *addr, assumed;
    do {
        assumed = old;
        unsigned short bits = hi ? (unsigned short)(assumed >> 16)
                                 : (unsigned short)(assumed & 0xffffu);
        __nv_bfloat16_raw r; r.x = bits;
        float cur = __bfloat162float((__nv_bfloat16)r);
        __nv_bfloat16 nb = __float2bfloat16_rn(cur + val);
        __nv_bfloat16_raw nr = static_cast<__nv_bfloat16_raw>(nb);
        uint32_t nw = hi ? ((assumed & 0x0000ffffu) | ((uint32_t)nr.x << 16))
                         : ((assumed & 0xffff0000u) | (uint32_t)nr.x);
        old = atomicCAS(addr, assumed, nw);
    } while (old != assumed);
}

__global__ void edge_bias_kernel(const float* __restrict__ edge_attr,
                                 const float* __restrict__ epw,
                                 const float* __restrict__ epb,
                                 const int* __restrict__ edge_index) {
    int e = blockIdx.x * blockDim.x + threadIdx.x;
    if (e >= EE) return;
    const float* ea = edge_attr + (size_t)e * EFD;
    int src = edge_index[e];
    int dst = edge_index[EE + e];
    int col = dst + 1;
    int p = col >> 1, hi = col & 1;
#pragma unroll
    for (int h = 0; h < HH; h++) {
        float pr = epb[h];
#pragma unroll
        for (int k = 0; k < EFD; k++) pr += ea[k] * epw[h * EFD + k];
        uint32_t* addr = &g_biasb[((size_t)h * NFT + src + 1) * BP + p];
        atomic_add_bf16half(addr, hi, pr);
    }
}

// ---------------------------------------------------------------------------
// warp-per-row layernorm
// ---------------------------------------------------------------------------
template <int SPLIT>
__global__ void ln_warp_kernel(const float* __restrict__ in,
                               float* __restrict__ outf,
                               uint32_t* __restrict__ oh, uint32_t* __restrict__ ol,
                               const float* __restrict__ s, const float* __restrict__ b) {
    int w = threadIdx.x >> 5, lane = threadIdx.x & 31;
    int row = blockIdx.x * 8 + w;
    if (row >= NFT) return;
    const float* p = in + (size_t)row * DD;
    float4 a = *(const float4*)&p[lane * 4];
    float4 c = *(const float4*)&p[128 + lane * 4];
    float sum = a.x + a.y + a.z + a.w + c.x + c.y + c.z + c.w;
#pragma unroll
    for (int o = 16; o > 0; o >>= 1) sum += __shfl_xor_sync(0xffffffffu, sum, o);
    float mean = sum * (1.0f / DD);
    float d0 = a.x - mean, d1 = a.y - mean, d2 = a.z - mean, d3 = a.w - mean;
    float d4 = c.x - mean, d5 = c.y - mean, d6 = c.z - mean, d7 = c.w - mean;
    float vs = d0 * d0 + d1 * d1 + d2 * d2 + d3 * d3 +
               d4 * d4 + d5 * d5 + d6 * d6 + d7 * d7;
#pragma unroll
    for (int o = 16; o > 0; o >>= 1) vs += __shfl_xor_sync(0xffffffffu, vs, o);
    float rstd = rsqrtf(vs * (1.0f / DD) + 1e-5f);
    int c0 = lane * 4, c1 = 128 + lane * 4;
    float o0 = d0 * rstd * s[c0 + 0] + b[c0 + 0];
    float o1 = d1 * rstd * s[c0 + 1] + b[c0 + 1];
    float o2 = d2 * rstd * s[c0 + 2] + b[c0 + 2];
    float o3 = d3 * rstd * s[c0 + 3] + b[c0 + 3];
    float o4 = d4 * rstd * s[c1 + 0] + b[c1 + 0];
    float o5 = d5 * rstd * s[c1 + 1] + b[c1 + 1];
    float o6 = d6 * rstd * s[c1 + 2] + b[c1 + 2];
    float o7 = d7 * rstd * s[c1 + 3] + b[c1 + 3];
    if (SPLIT) {
        uint32_t h, l;
        size_t base = (size_t)row * D2;
        split2(o0, o1, h, l); oh[base + 2 * lane] = h;      ol[base + 2 * lane] = l;
        split2(o2, o3, h, l); oh[base + 2 * lane + 1] = h;  ol[base + 2 * lane + 1] = l;
        split2(o4, o5, h, l); oh[base + 64 + 2 * lane] = h; ol[base + 64 + 2 * lane] = l;
        split2(o6, o7, h, l); oh[base + 65 + 2 * lane] = h; ol[base + 65 + 2 * lane] = l;
    } else {
        float* q = outf + (size_t)row * DD;
        *(float4*)&q[c0] = make_float4(o0, o1, o2, o3);
        *(float4*)&q[c1] = make_float4(o4, o5, o6, o7);
    }
}

// ---------------------------------------------------------------------------
// split GEMM with ldmatrix fragment loads (fp16 split, 3-MMA). Single-stage.
// MODE 0: split out. 1: fp32+res. 2: gelu+split. 3: fused-QKV epilogue.
// ---------------------------------------------------------------------------
template <int MODE>
__global__ void gemm_sp_kernel(const uint32_t* __restrict__ Ahg,
                               const uint32_t* __restrict__ Alg,
                               const uint32_t* __restrict__ Whg,
                               const uint32_t* __restrict__ Wlg,
                               const float* __restrict__ bias,
                               const float* __restrict__ res,
                               float* __restrict__ outf,
                               uint32_t* __restrict__ outh,
                               uint32_t* __restrict__ outl,
                               uint32_t* __restrict__ kh_, uint32_t* __restrict__ kl_,
                               uint32_t* __restrict__ vh_, uint32_t* __restrict__ vl_,
                               int M, int Ncol, int K) {
    __shared__ __align__(16) uint32_t Ah[64][20], Al[64][20];
    __shared__ __align__(16) uint32_t Bh[64][20], Bl[64][20];
    int K2 = K >> 1;
    int tid = threadIdx.x;
    int lane = tid & 31, wid = tid >> 5;
    int warpM = wid & 3, warpN = wid >> 2;
    int m0 = blockIdx.y * 64, n0 = blockIdx.x * 64;
    int g = lane >> 2, t = lane & 3;

    float c[4][4] = {};

    int lr = tid >> 2;
    int lq = (tid & 3) * 4;
    bool arow = (m0 + lr) < M;
    const uint4 z4 = make_uint4(0, 0, 0, 0);
    uint4 rah = arow ? *(const uint4*)&Ahg[(size_t)(m0 + lr) * K2 + lq] : z4;
    uint4 ral = arow ? *(const uint4*)&Alg[(size_t)(m0 + lr) * K2 + lq] : z4;
    uint4 rbh = *(const uint4*)&Whg[(size_t)(n0 + lr) * K2 + lq];
    uint4 rbl = *(const uint4*)&Wlg[(size_t)(n0 + lr) * K2 + lq];

    uint32_t a_h = smem_u32(&Ah[warpM * 16 + (lane & 15)][(lane >> 4) * 4]);
    uint32_t a_l = smem_u32(&Al[warpM * 16 + (lane & 15)][(lane >> 4) * 4]);
    int brow = warpN * 32 + (lane >> 4) * 8 + (lane & 7);
    int bseg = ((lane >> 3) & 1) * 4;
    uint32_t b_h0 = smem_u32(&Bh[brow][bseg]);
    uint32_t b_h1 = smem_u32(&Bh[brow + 16][bseg]);
    uint32_t b_l0 = smem_u32(&Bl[brow][bseg]);
    uint32_t b_l1 = smem_u32(&Bl[brow + 16][bseg]);

    for (int k0 = 0; k0 < K2; k0 += 16) {
        __syncthreads();
        Ah[lr][lq] = rah.x; Ah[lr][lq + 1] = rah.y; Ah[lr][lq + 2] = rah.z; Ah[lr][lq + 3] = rah.w;
        Al[lr][lq] = ral.x; Al[lr][lq + 1] = ral.y; Al[lr][lq + 2] = ral.z; Al[lr][lq + 3] = ral.w;
        Bh[lr][lq] = rbh.x; Bh[lr][lq + 1] = rbh.y; Bh[lr][lq + 2] = rbh.z; Bh[lr][lq + 3] = rbh.w;
        Bl[lr][lq] = rbl.x; Bl[lr][lq + 1] = rbl.y; Bl[lr][lq + 2] = rbl.z; Bl[lr][lq + 3] = rbl.w;
        __syncthreads();
        if (k0 + 16 < K2) {
            rah = arow ? *(const uint4*)&Ahg[(size_t)(m0 + lr) * K2 + k0 + 16 + lq] : z4;
            ral = arow ? *(const uint4*)&Alg[(size_t)(m0 + lr) * K2 + k0 + 16 + lq] : z4;
            rbh = *(const uint4*)&Whg[(size_t)(n0 + lr) * K2 + k0 + 16 + lq];
            rbl = *(const uint4*)&Wlg[(size_t)(n0 + lr) * K2 + k0 + 16 + lq];
        }
#pragma unroll
        for (int kk = 0; kk < 2; kk++) {
            uint32_t koff = kk * 32;
            uint32_t ah0, ah1, ah2, ah3, al0, al1, al2, al3;
            ldsm_x4(ah0, ah1, ah2, ah3, a_h + koff);
            ldsm_x4(al0, al1, al2, al3, a_l + koff);
            uint32_t bh[8], bl[8];
            ldsm_x4(bh[0], bh[1], bh[2], bh[3], b_h0 + koff);
            ldsm_x4(bh[4], bh[5], bh[6], bh[7], b_h1 + koff);
            ldsm_x4(bl[0], bl[1], bl[2], bl[3], b_l0 + koff);
            ldsm_x4(bl[4], bl[5], bl[6], bl[7], b_l1 + koff);
#pragma unroll
            for (int ni = 0; ni < 4; ni++) {
                uint32_t b0h = bh[ni * 2], b1h = bh[ni * 2 + 1];
                uint32_t b0l = bl[ni * 2], b1l = bl[ni * 2 + 1];
                mma_hf(c[ni], ah0, ah1, ah2, ah3, b0h, b1h);
                mma_hf(c[ni], ah0, ah1, ah2, ah3, b0l, b1l);
                mma_hf(c[ni], al0, al1, al2, al3, b0h, b1h);
            }
        }
    }

    int N2 = Ncol >> 1;
#pragma unroll
    for (int ni = 0; ni < 4; ni++) {
        int col = n0 + warpN * 32 + ((ni < 2) ? 0 : 16) + (ni & 1) * 8 + t * 2;
        float b0 = bias[col], b1 = bias[col + 1];
#pragma unroll
        for (int half = 0; half < 2; half++) {
            int r = m0 + warpM * 16 + g + half * 8;
            if (r >= M) continue;
            float v0 = c[ni][half * 2 + 0] + b0;
            float v1 = c[ni][half * 2 + 1] + b1;
            if (MODE == 2) {
                v0 = 0.5f * v0 * (1.0f + erff(v0 * 0.7071067811865475f));
                v1 = 0.5f * v1 * (1.0f + erff(v1 * 0.7071067811865475f));
            }
            if (MODE == 1) {
                outf[(size_t)r * Ncol + col] = v0 + res[(size_t)r * Ncol + col];
                outf[(size_t)r * Ncol + col + 1] = v1 + res[(size_t)r * Ncol + col + 1];
            } else if (MODE == 3) {
                int buf = col >> 8, cc = col & 255;
                uint32_t* ph = (buf == 0) ? outh : (buf == 1) ? kh_ : vh_;
                uint32_t* pl = (buf == 0) ? outl : (buf == 1) ? kl_ : vl_;
                uint32_t hw, lw;
                split2(v0, v1, hw, lw);
                ph[(size_t)r * D2 + (cc >> 1)] = hw;
                pl[(size_t)r * D2 + (cc >> 1)] = lw;
            } else {
                uint32_t hw, lw;
                split2(v0, v1, hw, lw);
                outh[(size_t)r * N2 + (col >> 1)] = hw;
                outl[(size_t)r * N2 + (col >> 1)] = lw;
            }
        }
    }
}

// ---------------------------------------------------------------------------
// fused flash attention (fp16 split; P direct fp16). 64 q-rows, 128 threads.
// ---------------------------------------------------------------------------
__global__ void __launch_bounds__(128)
attn_kernel(const uint32_t* __restrict__ Qh, const uint32_t* __restrict__ Ql,
            const uint32_t* __restrict__ Khg, const uint32_t* __restrict__ Klg,
            const uint32_t* __restrict__ Vhg, const uint32_t* __restrict__ Vlg,
            const uint32_t* __restrict__ biasb,
            uint32_t* __restrict__ Oh, uint32_t* __restrict__ Ol) {
    __shared__ __align__(16) uint32_t Ksh[64][20], Ksl[64][20];
    __shared__ __align__(16) uint32_t Vsh[32][36], Vsl[32][36];

    int tid = threadIdx.x;
    int lane = tid & 31, w = tid >> 5;
    int g = lane >> 2, t = lane & 3;
    int z = blockIdx.y;
    int i0 = blockIdx.x * 64;
    int r0 = i0 + w * 16 + g;
    int r1 = r0 + 8;

    uint32_t qh[2][4], ql[2][4];
#pragma unroll
    for (int kk = 0; kk < 2; kk++) {
#pragma unroll
        for (int j = 0; j < 4; j++) {
            int rr = r0 + (j & 1) * 8;
            int pi = z * 16 + kk * 8 + (j >> 1) * 4 + t;
            qh[kk][j] = (rr < NFT) ? Qh[(size_t)rr * D2 + pi] : 0u;
            ql[kk][j] = (rr < NFT) ? Ql[(size_t)rr * D2 + pi] : 0u;
        }
    }

    float m[2] = {-1e30f, -1e30f}, l[2] = {0.f, 0.f};
    float co[4][4] = {};

    int lkey = tid >> 1;
    int lhalf = (tid & 1) * 8;
    int kp = tid >> 2;
    int hp = (tid & 3) * 4;

    const float inv = 0.17677669529663687f;
    int br0 = min(r0, NFT - 1), br1 = min(r1, NFT - 1);
    const uint32_t* bp0 = biasb + ((size_t)z * NFT + br0) * BP;
    const uint32_t* bp1 = biasb + ((size_t)z * NFT + br1) * BP;

    int krow = (lane >> 4) * 8 + (lane & 7);
    int kseg = ((lane >> 3) & 1) * 4;
    uint32_t k_h[4], k_l[4];
#pragma unroll
    for (int gg = 0; gg < 4; gg++) {
        k_h[gg] = smem_u32(&Ksh[gg * 16 + krow][kseg]);
        k_l[gg] = smem_u32(&Ksl[gg * 16 + krow][kseg]);
    }
    uint32_t v_h[2], v_l[2];
#pragma unroll
    for (int gg = 0; gg < 2; gg++) {
        v_h[gg] = smem_u32(&Vsh[gg * 16 + krow][kseg]);
        v_l[gg] = smem_u32(&Vsl[gg * 16 + krow][kseg]);
    }

    const uint4 z4 = make_uint4(0, 0, 0, 0);
    uint4 rkh0, rkh1, rkl0, rkl1, vah, val_, vbh, vbl;
    {
        bool kv = lkey < NFT;
        const uint32_t* kb = &Khg[(size_t)lkey * D2 + z * 16 + lhalf];
        const uint32_t* lb = &Klg[(size_t)lkey * D2 + z * 16 + lhalf];
        rkh0 = kv ? *(const uint4*)kb : z4;
        rkh1 = kv ? *(const uint4*)(kb + 4) : z4;
        rkl0 = kv ? *(const uint4*)lb : z4;
        rkl1 = kv ? *(const uint4*)(lb + 4) : z4;
        int ra = 2 * kp, rb = 2 * kp + 1;
        vah = (ra < NFT) ? *(const uint4*)&Vhg[(size_t)ra * D2 + z * 16 + hp] : z4;
        val_ = (ra < NFT) ? *(const uint4*)&Vlg[(size_t)ra * D2 + z * 16 + hp] : z4;
        vbh = (rb < NFT) ? *(const uint4*)&Vhg[(size_t)rb * D2 + z * 16 + hp] : z4;
        vbl = (rb < NFT) ? *(const uint4*)&Vlg[(size_t)rb * D2 + z * 16 + hp] : z4;
    }

    for (int jt = 0; jt < 33; jt++) {
        int j0 = jt * 64;
        __syncthreads();
        {
            Ksh[lkey][lhalf + 0] = rkh0.x; Ksh[lkey][lhalf + 1] = rkh0.y;
            Ksh[lkey][lhalf + 2] = rkh0.z; Ksh[lkey][lhalf + 3] = rkh0.w;
            Ksh[lkey][lhalf + 4] = rkh1.x; Ksh[lkey][lhalf + 5] = rkh1.y;
            Ksh[lkey][lhalf + 6] = rkh1.z; Ksh[lkey][lhalf + 7] = rkh1.w;
            Ksl[lkey][lhalf + 0] = rkl0.x; Ksl[lkey][lhalf + 1] = rkl0.y;
            Ksl[lkey][lhalf + 2] = rkl0.z; Ksl[lkey][lhalf + 3] = rkl0.w;
            Ksl[lkey][lhalf + 4] = rkl1.x; Ksl[lkey][lhalf + 5] = rkl1.y;
            Ksl[lkey][lhalf + 6] = rkl1.z; Ksl[lkey][lhalf + 7] = rkl1.w;
            Vsh[2 * hp + 0][kp] = __byte_perm(vah.x, vbh.x, 0x5410);
            Vsh[2 * hp + 1][kp] = __byte_perm(vah.x, vbh.x, 0x7632);
            Vsh[2 * hp + 2][kp] = __byte_perm(vah.y, vbh.y, 0x5410);
            Vsh[2 * hp + 3][kp] = __byte_perm(vah.y, vbh.y, 0x7632);
            Vsh[2 * hp + 4][kp] = __byte_perm(vah.z, vbh.z, 0x5410);
            Vsh[2 * hp + 5][kp] = __byte_perm(vah.z, vbh.z, 0x7632);
            Vsh[2 * hp + 6][kp] = __byte_perm(vah.w, vbh.w, 0x5410);
            Vsh[2 * hp + 7][kp] = __byte_perm(vah.w, vbh.w, 0x7632);
            Vsl[2 * hp + 0][kp] = __byte_perm(val_.x, vbl.x, 0x5410);
            Vsl[2 * hp + 1][kp] = __byte_perm(val_.x, vbl.x, 0x7632);
            Vsl[2 * hp + 2][kp] = __byte_perm(val_.y, vbl.y, 0x5410);
            Vsl[2 * hp + 3][kp] = __byte_perm(val_.y, vbl.y, 0x7632);
            Vsl[2 * hp + 4][kp] = __byte_perm(val_.z, vbl.z, 0x5410);
            Vsl[2 * hp + 5][kp] = __byte_perm(val_.z, vbl.z, 0x7632);
            Vsl[2 * hp + 6][kp] = __byte_perm(val_.w, vbl.w, 0x5410);
            Vsl[2 * hp + 7][kp] = __byte_perm(val_.w, vbl.w, 0x7632);
        }
        __syncthreads();
        if (jt + 1 < 33) {
            int n0 = (jt + 1) * 64;
            bool kv = n0 + lkey < NFT;
            const uint32_t* kb = &Khg[(size_t)(n0 + lkey) * D2 + z * 16 + lhalf];
            const uint32_t* lb = &Klg[(size_t)(n0 + lkey) * D2 + z * 16 + lhalf];
            rkh0 = kv ? *(const uint4*)kb : z4;
            rkh1 = kv ? *(const uint4*)(kb + 4) : z4;
            rkl0 = kv ? *(const uint4*)lb : z4;
            rkl1 = kv ? *(const uint4*)(lb + 4) : z4;
            int ra = n0 + 2 * kp, rb = ra + 1;
            vah = (ra < NFT) ? *(const uint4*)&Vhg[(size_t)ra * D2 + z * 16 + hp] : z4;
            val_ = (ra < NFT) ? *(const uint4*)&Vlg[(size_t)ra * D2 + z * 16 + hp] : z4;
            vbh = (rb < NFT) ? *(const uint4*)&Vhg[(size_t)rb * D2 + z * 16 + hp] : z4;
            vbl = (rb < NFT) ? *(const uint4*)&Vlg[(size_t)rb * D2 + z * 16 + hp] : z4;
        }

        // S = Q @ K^T
        float cs[8][4] = {};
#pragma unroll
        for (int kk = 0; kk < 2; kk++) {
            uint32_t koff = kk * 32;
#pragma unroll
            for (int gg = 0; gg < 4; gg++) {
                uint32_t f0, f1, f2, f3, e0, e1, e2, e3;
                ldsm_x4(f0, f1, f2, f3, k_h[gg] + koff);
                ldsm_x4(e0, e1, e2, e3, k_l[gg] + koff);
                mma_hf(cs[2 * gg], qh[kk][0], qh[kk][1], qh[kk][2], qh[kk][3], f0, f1);
                mma_hf(cs[2 * gg], qh[kk][0], qh[kk][1], qh[kk][2], qh[kk][3], e0, e1);
                mma_hf(cs[2 * gg], ql[kk][0], ql[kk][1], ql[kk][2], ql[kk][3], f0, f1);
                mma_hf(cs[2 * gg + 1], qh[kk][0], qh[kk][1], qh[kk][2], qh[kk][3], f2, f3);
                mma_hf(cs[2 * gg + 1], qh[kk][0], qh[kk][1], qh[kk][2], qh[kk][3], e2, e3);
                mma_hf(cs[2 * gg + 1], ql[kk][0], ql[kk][1], ql[kk][2], ql[kk][3], f2, f3);
            }
        }

        // scale + bias + guards
#pragma unroll
        for (int ni = 0; ni < 8; ni++) {
            int gg = ni >> 1;
            int col = j0 + gg * 16 + (ni & 1) * 8 + t * 2;
            int pidx = (col >> 1);
            union { uint32_t u; __nv_bfloat162 v; } w0, w1;
            w0.u = bp0[pidx]; w1.u = bp1[pidx];
            float2 f0 = __bfloat1622float2(w0.v);
            float2 f1 = __bfloat1622float2(w1.v);
            bool v0 = col < NFT, v1 = col + 1 < NFT;
            cs[ni][0] = v0 ? cs[ni][0] * inv + f0.x : -1e30f;
            cs[ni][1] = v1 ? cs[ni][1] * inv + f0.y : -1e30f;
            cs[ni][2] = v0 ? cs[ni][2] * inv + f1.x : -1e30f;
            cs[ni][3] = v1 ? cs[ni][3] * inv + f1.y : -1e30f;
        }

        // online softmax
#pragma unroll
        for (int hh = 0; hh < 2; hh++) {
            int c0 = hh * 2;
            float mx = -1e30f;
#pragma unroll
            for (int ni = 0; ni < 8; ni++)
                mx = fmaxf(mx, fmaxf(cs[ni][c0], cs[ni][c0 + 1]));
            mx = fmaxf(mx, __shfl_xor_sync(0xffffffffu, mx, 1));
            mx = fmaxf(mx, __shfl_xor_sync(0xffffffffu, mx, 2));
            float mn = fmaxf(m[hh], mx);
            float corr = __expf(m[hh] - mn);
            m[hh] = mn;
            l[hh] *= corr;
#pragma unroll
            for (int ni = 0; ni < 4; ni++) {
                co[ni][c0] *= corr;
                co[ni][c0 + 1] *= corr;
            }
            float sum = 0.f;
#pragma unroll
            for (int ni = 0; ni < 8; ni++) {
                float p0 = __expf(cs[ni][c0] - mn);
                float p1 = __expf(cs[ni][c0 + 1] - mn);
                cs[ni][c0] = p0; cs[ni][c0 + 1] = p1;
                sum += p0 + p1;
            }
            sum += __shfl_xor_sync(0xffffffffu, sum, 1);
            sum += __shfl_xor_sync(0xffffffffu, sum, 2);
            l[hh] += sum;
        }

        // O += P @ V : P direct fp16
#pragma unroll
        for (int kk = 0; kk < 4; kk++) {
            uint32_t a0 = pack_h2(cs[2 * kk][0], cs[2 * kk][1]);
            uint32_t a1 = pack_h2(cs[2 * kk][2], cs[2 * kk][3]);
            uint32_t a2 = pack_h2(cs[2 * kk + 1][0], cs[2 * kk + 1][1]);
            uint32_t a3 = pack_h2(cs[2 * kk + 1][2], cs[2 * kk + 1][3]);
            uint32_t koff = kk * 32;
#pragma unroll
            for (int gg = 0; gg < 2; gg++) {
                uint32_t f0, f1, f2, f3, e0, e1, e2, e3;
                ldsm_x4(f0, f1, f2, f3, v_h[gg] + koff);
                ldsm_x4(e0, e1, e2, e3, v_l[gg] + koff);
                mma_hf(co[2 * gg], a0, a1, a2, a3, f0, f1);
                mma_hf(co[2 * gg], a0, a1, a2, a3, e0, e1);
                mma_hf(co[2 * gg + 1], a0, a1, a2, a3, f2, f3);
                mma_hf(co[2 * gg + 1], a0, a1, a2, a3, e2, e3);
            }
        }
    }

    float inv0 = 1.f / l[0], inv1 = 1.f / l[1];
#pragma unroll
    for (int ni = 0; ni < 4; ni++) {
        int cc = (ni >> 1) * 16 + (ni & 1) * 8 + t * 2;
        int pi = z * 16 + (cc >> 1);
        if (r0 < NFT) {
            uint32_t hw, lw;
            split2(co[ni][0] * inv0, co[ni][1] * inv0, hw, lw);
            Oh[(size_t)r0 * D2 + pi] = hw;
            Ol[(size_t)r0 * D2 + pi] = lw;
        }
        if (r1 < NFT) {
            uint32_t hw, lw;
            split2(co[ni][2] * inv1, co[ni][3] * inv1, hw, lw);
            Oh[(size_t)r1 * D2 + pi] = hw;
            Ol[(size_t)r1 * D2 + pi] = lw;
        }
    }
}

// ---------------------------------------------------------------------------
// launch
// ---------------------------------------------------------------------------
extern "C" void kernel_launch(void* const* d_in, const int* in_sizes, int n_in,
                              void* d_out, int out_size) {
    const float* x            = (const float*)d_in[0];
    const float* edge_attr    = (const float*)d_in[1];
    const float* node_proj_w  = (const float*)d_in[2];
    const float* node_proj_b  = (const float*)d_in[3];
    const float* in_deg_emb   = (const float*)d_in[4];
    const float* out_deg_emb  = (const float*)d_in[5];
    const float* dist_bias    = (const float*)d_in[6];
    const float* edge_proj_w  = (const float*)d_in[7];
    const float* edge_proj_b  = (const float*)d_in[8];
    const float* cls_token    = (const float*)d_in[9];
    const float* q_w = (const float*)d_in[10];
    const float* q_b = (const float*)d_in[11];
    const float* k_w = (const float*)d_in[12];
    const float* k_b = (const float*)d_in[13];
    const float* v_w = (const float*)d_in[14];
    const float* v_b = (const float*)d_in[15];
    const float* o_w = (const float*)d_in[16];
    const float* o_b = (const float*)d_in[17];
    const float* ffn1_w = (const float*)d_in[18];
    const float* ffn1_b = (const float*)d_in[19];
    const float* ffn2_w = (const float*)d_in[20];
    const float* ffn2_b = (const float*)d_in[21];
    const float* ln1_s = (const float*)d_in[22];
    const float* ln1_b = (const float*)d_in[23];
    const float* ln2_s = (const float*)d_in[24];
    const float* ln2_b = (const float*)d_in[25];
    const float* fn_s = (const float*)d_in[26];
    const float* fn_b = (const float*)d_in[27];
    const int* edge_index  = (const int*)d_in[28];
    const int* dist_matrix = (const int*)d_in[29];
    float* out = (float*)d_out;

    float *h, *fin, *qkvb;
    uint32_t *hnh, *hnl, *qh, *ql, *kh, *kl, *vh, *vl, *oh, *ol, *fh, *fl;
    uint32_t *wh, *wl, *biasb;
    cudaGetSymbolAddress((void**)&h, g_h);
    cudaGetSymbolAddress((void**)&fin, g_fin);
    cudaGetSymbolAddress((void**)&hnh, g_hnh); cudaGetSymbolAddress((void**)&hnl, g_hnl);
    cudaGetSymbolAddress((void**)&qh, g_qh); cudaGetSymbolAddress((void**)&ql, g_ql);
    cudaGetSymbolAddress((void**)&kh, g_kh); cudaGetSymbolAddress((void**)&kl, g_kl);
    cudaGetSymbolAddress((void**)&vh, g_vh); cudaGetSymbolAddress((void**)&vl, g_vl);
    cudaGetSymbolAddress((void**)&oh, g_oh); cudaGetSymbolAddress((void**)&ol, g_ol);
    cudaGetSymbolAddress((void**)&fh, g_fh); cudaGetSymbolAddress((void**)&fl, g_fl);
    cudaGetSymbolAddress((void**)&wh, g_wh); cudaGetSymbolAddress((void**)&wl, g_wl);
    cudaGetSymbolAddress((void**)&biasb, g_biasb);
    cudaGetSymbolAddress((void**)&qkvb, g_qkvb);

    const int PQKV = LL * 768 * 128;
    const int DQ = LL * DD * DD / 2;
    const int DF = LL * FFND * DD / 2;
    split_qkv_kernel<<<(PQKV + 255) / 256, 256>>>(q_w, k_w, v_w, wh + WOFF_QKV, wl + WOFF_QKV);
    qkvb_prep_kernel<<<(LL * 768 + 255) / 256, 256>>>(q_b, k_b, v_b);
    split_prep_kernel<<<(DQ + 255) / 256, 256>>>(o_w, wh + WOFF_O, wl + WOFF_O, DQ);
    split_prep_kernel<<<(DF + 255) / 256, 256>>>(ffn1_w, wh + WOFF_F1, wl + WOFF_F1, DF);
    split_prep_kernel<<<(DF + 255) / 256, 256>>>(ffn2_w, wh + WOFF_F2, wl + WOFF_F2, DF);

    zero_deg_kernel<<<(NN + 255) / 256, 256>>>();
    count_deg_kernel<<<(EE + 255) / 256, 256>>>(edge_index);
    node_embed_kernel<<<NN, 256>>>(x, node_proj_w, node_proj_b, in_deg_emb, out_deg_emb);
    cls_kernel<<<1, 256>>>(cls_token);

    int nfill = NFT * BP;
    bias_fillb_kernel<<<(nfill + 255) / 256, 256>>>(dist_matrix, dist_bias);
    edge_bias_kernel<<<(EE + 255) / 256, 256>>>(edge_attr, edge_proj_w, edge_proj_b,
                                                edge_index);

    dim3 gemmQKV(12, 33);
    dim3 gemmD(4, 33);
    dim3 gemmF1(16, 33);
    dim3 attnG(33, 8);
    int lnG = (NFT + 7) / 8;

    for (int l = 0; l < LL; l++) {
        ln_warp_kernel<1><<<lnG, 256>>>(h, nullptr, hnh, hnl,
                                        ln1_s + l * DD, ln1_b + l * DD);
        gemm_sp_kernel<3><<<gemmQKV, 256>>>(hnh, hnl,
                                            wh + WOFF_QKV + (size_t)l * 98304,
                                            wl + WOFF_QKV + (size_t)l * 98304,
                                            qkvb + l * 768, nullptr, nullptr,
                                            qh, ql, kh, kl, vh, vl,
                                            NFT, 768, DD);
        attn_kernel<<<attnG, 128>>>(qh, ql, kh, kl, vh, vl, biasb, oh, ol);
        gemm_sp_kernel<1><<<gemmD, 256>>>(oh, ol,
                                          wh + WOFF_O + (size_t)l * 32768,
                                          wl + WOFF_O + (size_t)l * 32768,
                                          o_b + l * DD, h, h, nullptr, nullptr,
                                          nullptr, nullptr, nullptr, nullptr,
                                          NFT, DD, DD);
        ln_warp_kernel<1><<<lnG, 256>>>(h, nullptr, hnh, hnl,
                                        ln2_s + l * DD, ln2_b + l * DD);
        gemm_sp_kernel<2><<<gemmF1, 256>>>(hnh, hnl,
                                           wh + WOFF_F1 + (size_t)l * 131072,
                                           wl + WOFF_F1 + (size_t)l * 131072,
                                           ffn1_b + l * FFND, nullptr, nullptr, fh, fl,
                                           nullptr, nullptr, nullptr, nullptr,
                                           NFT, FFND, DD);
        gemm_sp_kernel<1><<<gemmD, 256>>>(fh, fl,
                                          wh + WOFF_F2 + (size_t)l * 131072,
                                          wl + WOFF_F2 + (size_t)l * 131072,
                                          ffn2_b + l * DD, h, h, nullptr, nullptr,
                                          nullptr, nullptr, nullptr, nullptr,
                                          NFT, DD, FFND);
    }

    ln_warp_kernel<0><<<lnG, 256>>>(h, fin, nullptr, nullptr, fn_s, fn_b);
    size_t total = (size_t)NFT * DD;
    if ((size_t)out_size >= total + DD) {
        cudaMemcpyAsync(out, fin, total * sizeof(float), cudaMemcpyDeviceToDevice);
        cudaMemcpyAsync(out + total, fin, DD * sizeof(float), cudaMemcpyDeviceToDevice);
    } else if ((size_t)out_size >= total) {
        cudaMemcpyAsync(out, fin, total * sizeof(float), cudaMemcpyDeviceToDevice);
    } else {
        cudaMemcpyAsync(out, fin, (size_t)out_size * sizeof(float),
                        cudaMemcpyDeviceToDevice);
    }
}